// round 8
// baseline (speedup 1.0000x reference)
#include <cuda_runtime.h>
#include <cuda_fp16.h>
#include <math.h>
#include <stdint.h>

#define D_MODEL 2048
#define D_HID   256
#define N_HEADS 16
#define WINDOW  64
#define MAX_TOK 131072

// ---------------- device scratch (no allocs allowed) ----------------
__device__ float    g_L [(size_t)MAX_TOK * N_HEADS];
__device__ float    g_Vv[(size_t)MAX_TOK * N_HEADS];
__device__ __half   g_w1h[(size_t)D_HID * D_MODEL];   // w1 transposed+fp16 [256][2048]
__device__ __half   g_qvh[32 * D_HID];                // [16 q | 16 v heads][256] fp16
__device__ unsigned g_logit_max[N_HEADS];
__device__ unsigned g_score_max[N_HEADS];

// ---------------- helpers ----------------
__device__ __forceinline__ unsigned f2ord(float f){
    unsigned u = __float_as_uint(f);
    return (u & 0x80000000u) ? ~u : (u | 0x80000000u);
}
__device__ __forceinline__ float ord2f(unsigned u){
    return (u & 0x80000000u) ? __uint_as_float(u & 0x7fffffffu) : __uint_as_float(~u);
}
__device__ __forceinline__ uint32_t smem_u32(const void* p){
    uint32_t a;
    asm("{ .reg .u64 t; cvta.to.shared.u64 t, %1; cvt.u32.u64 %0, t; }" : "=r"(a) : "l"(p));
    return a;
}
__device__ __forceinline__ uint32_t pack_h2(float lo, float hi){
    __half2 h = __floats2half2_rn(lo, hi);
    return *reinterpret_cast<uint32_t*>(&h);
}
__device__ __forceinline__ void mma16816(float* c, const uint32_t* a, const uint32_t* b){
    asm volatile(
        "mma.sync.aligned.m16n8k16.row.col.f32.f16.f16.f32 "
        "{%0,%1,%2,%3}, {%4,%5,%6,%7}, {%8,%9}, {%0,%1,%2,%3};"
        : "+f"(c[0]), "+f"(c[1]), "+f"(c[2]), "+f"(c[3])
        : "r"(a[0]), "r"(a[1]), "r"(a[2]), "r"(a[3]), "r"(b[0]), "r"(b[1]));
}
#define LDMX4(r0, r1, r2, r3, addr) \
    asm volatile("ldmatrix.sync.aligned.m8n8.x4.shared.b16 {%0,%1,%2,%3}, [%4];" \
                 : "=r"(r0), "=r"(r1), "=r"(r2), "=r"(r3) : "r"(addr))

// ---------------- kernels ----------------
__global__ void k_init(){
    int t = threadIdx.x;
    if (t < N_HEADS){
        unsigned ninf = ~0xFF800000u;  // f2ord(-inf)
        g_logit_max[t] = ninf;
        g_score_max[t] = ninf;
    }
}

// w1 [2048][256] fp32 -> g_w1h [256][2048] fp16
__global__ void k_prep_w(const float* __restrict__ w1){
    __shared__ float t[32][33];
    int k0 = blockIdx.x * 32, n0 = blockIdx.y * 32;
    int tx = threadIdx.x, ty = threadIdx.y;     // 32 x 8
    #pragma unroll
    for (int i = ty; i < 32; i += 8)
        t[i][tx] = w1[(size_t)(k0 + i) * D_HID + n0 + tx];
    __syncthreads();
    #pragma unroll
    for (int i = ty; i < 32; i += 8)
        g_w1h[(size_t)(n0 + i) * D_MODEL + k0 + tx] = __float2half_rn(t[tx][i]);
}

// qw,vw [16][256] fp32 -> g_qvh [32][256] fp16
__global__ void k_prep_qv(const float* __restrict__ qw, const float* __restrict__ vw){
    int i = blockIdx.x * 256 + threadIdx.x;
    if (i < 4096)      g_qvh[i] = __float2half_rn(qw[i]);
    else if (i < 8192) g_qvh[i] = __float2half_rn(vw[i - 4096]);
}

// ---------------- fused MLP + head projection (HMMA) ----------------
#define BK          32
#define KT_TILES    (D_MODEL / BK)      // 64
#define A32_PITCH   144
#define B_STRIDE    80
#define A16_PITCH   80
#define A32_BYTES   (128 * A32_PITCH)   // 18432
#define B_BYTES     (256 * B_STRIDE)    // 20480
#define STAGE_BYTES (A32_BYTES + B_BYTES)   // 38912
#define N_STAGES    4
#define A16_BYTES   (128 * A16_PITCH)   // 10240
#define A16_OFF     (N_STAGES * STAGE_BYTES)        // 155648
#define SMEM_DYN    (A16_OFF + 2 * A16_BYTES)       // 176128

__device__ __forceinline__ void load_stage(const float* __restrict__ x, size_t m0,
                                           int kt, uint32_t sA, uint32_t sB, int tid){
    #pragma unroll
    for (int i = 0; i < 2; i++){
        int ch  = tid + i * 512;            // 0..1023
        int row = ch >> 3, c = ch & 7;      // A: 128 rows x 8 chunks of 16B
        const float* src = x + (m0 + row) * D_MODEL + (size_t)kt * BK + c * 4;
        uint32_t dst = sA + row * A32_PITCH + c * 16;
        asm volatile("cp.async.cg.shared.global [%0], [%1], 16;" :: "r"(dst), "l"(src));
    }
    #pragma unroll
    for (int i = 0; i < 2; i++){
        int ch  = tid + i * 512;            // 0..1023
        // conflict-free mapping: per 8-lane phase, 8 distinct rows (quads 5*l mod 8)
        int row = ((ch >> 5) << 3) + (ch & 7);   // 0..255
        int cc  = (ch >> 3) & 3;                 // 0..3
        const char* src = (const char*)g_w1h + (size_t)row * (D_MODEL * 2) + kt * (BK * 2) + cc * 16;
        uint32_t dst = sB + row * B_STRIDE + cc * 16;
        asm volatile("cp.async.cg.shared.global [%0], [%1], 16;" :: "r"(dst), "l"(src));
    }
}

// CTA-cooperative fp32 -> fp16 conversion of one 128x32 A tile
__device__ __forceinline__ void convert_tile(const char* stage, char* a16, int tid){
    int row = tid & 127;
    int cg  = tid >> 7;                     // 0..3 (8-float group)
    const float4* p = (const float4*)(stage + row * A32_PITCH + cg * 32);
    float4 v0 = p[0], v1 = p[1];
    uint4 o;
    o.x = pack_h2(v0.x, v0.y); o.y = pack_h2(v0.z, v0.w);
    o.z = pack_h2(v1.x, v1.y); o.w = pack_h2(v1.z, v1.w);
    *(uint4*)(a16 + row * A16_PITCH + cg * 16) = o;
}

__global__ __launch_bounds__(512, 1)
void k_mlp(const float* __restrict__ x, const float* __restrict__ b1)
{
    extern __shared__ __align__(16) char dyn[];
    __shared__ unsigned smax[N_HEADS];

    const int tid  = threadIdx.x;
    const int wid  = tid >> 5;
    const int lane = tid & 31;
    const int mw   = wid >> 2;      // 0..3  M warp
    const int nw   = wid & 3;       // 0..3  N warp
    const int rq   = lane >> 2;     // 0..7
    const int cq   = (lane & 3) * 2;
    const int m_   = lane >> 3;     // ldmatrix matrix id
    const int r_   = lane & 7;      // ldmatrix row
    const size_t m0 = (size_t)blockIdx.x * 128;

    const uint32_t dbase = smem_u32(dyn);
    if (tid < N_HEADS) smax[tid] = ~0xFF800000u;

    float acc[2][8][4];
    #pragma unroll
    for (int mt = 0; mt < 2; mt++)
        #pragma unroll
        for (int nt = 0; nt < 8; nt++)
            #pragma unroll
            for (int k = 0; k < 4; k++) acc[mt][nt][k] = 0.f;

    // prologue: 3 stages in flight, convert tile 0
    #pragma unroll
    for (int p = 0; p < 3; p++){
        uint32_t st = dbase + p * STAGE_BYTES;
        load_stage(x, m0, p, st, st + A32_BYTES, tid);
        asm volatile("cp.async.commit_group;" ::: "memory");
    }
    asm volatile("cp.async.wait_group 2;" ::: "memory");
    __syncthreads();
    convert_tile(dyn, dyn + A16_OFF, tid);

    for (int kt = 0; kt < KT_TILES; kt++){
        asm volatile("cp.async.wait_group 1;" ::: "memory");
        __syncthreads();   // publishes: stage kt+1 data, A16[kt&1]; frees A16[(kt+1)&1]

        const uint32_t sB  = dbase + (kt % N_STAGES) * STAGE_BYTES + A32_BYTES;
        const uint32_t sAh = dbase + A16_OFF + (kt & 1) * A16_BYTES;

        // 1) all fragment loads first (tensor pipe fed ASAP once latency drains)
        uint32_t bf[2][8][2], af[2][2][4];
        #pragma unroll
        for (int ks = 0; ks < 2; ks++){
            #pragma unroll
            for (int ng = 0; ng < 4; ng++){
                int nrow = nw * 64 + ng * 16 + ((m_ >> 1) * 8) + r_;
                uint32_t addr = sB + nrow * B_STRIDE + (ks * 16 + (m_ & 1) * 8) * 2;
                LDMX4(bf[ks][ng*2][0], bf[ks][ng*2][1],
                      bf[ks][ng*2+1][0], bf[ks][ng*2+1][1], addr);
            }
            #pragma unroll
            for (int mt = 0; mt < 2; mt++){
                int arow = mw * 32 + mt * 16 + (m_ & 1) * 8 + r_;
                uint32_t aaddr = sAh + arow * A16_PITCH + (ks * 16 + (m_ >> 1) * 8) * 2;
                LDMX4(af[ks][mt][0], af[ks][mt][1], af[ks][mt][2], af[ks][mt][3], aaddr);
            }
        }

        // 2) convert next A tile (hides LDSM latency)
        if (kt + 1 < KT_TILES)
            convert_tile(dyn + ((kt + 1) % N_STAGES) * STAGE_BYTES,
                         dyn + A16_OFF + ((kt + 1) & 1) * A16_BYTES, tid);

        // 3) refill pipeline
        if (kt + 3 < KT_TILES){
            uint32_t ns = dbase + ((kt + 3) % N_STAGES) * STAGE_BYTES;
            load_stage(x, m0, kt + 3, ns, ns + A32_BYTES, tid);
        }
        asm volatile("cp.async.commit_group;" ::: "memory");

        // 4) dense MMA burst
        #pragma unroll
        for (int ks = 0; ks < 2; ks++)
            #pragma unroll
            for (int mt = 0; mt < 2; mt++)
                #pragma unroll
                for (int nt = 0; nt < 8; nt++)
                    mma16816(acc[mt][nt], af[ks][mt], bf[ks][nt]);
    }
    asm volatile("cp.async.wait_group 0;" ::: "memory");
    __syncthreads();   // mainloop smem reads done; reuse dyn below

    // ---------------- epilogue: bias + relu, then projection MMA ----------------
    #pragma unroll
    for (int nt = 0; nt < 8; nt++){
        int C = nw * 64 + nt * 8 + cq;
        float bv0 = __ldg(b1 + C), bv1 = __ldg(b1 + C + 1);
        #pragma unroll
        for (int mt = 0; mt < 2; mt++){
            acc[mt][nt][0] = fmaxf(acc[mt][nt][0] + bv0, 0.f);
            acc[mt][nt][1] = fmaxf(acc[mt][nt][1] + bv1, 0.f);
            acc[mt][nt][2] = fmaxf(acc[mt][nt][2] + bv0, 0.f);
            acc[mt][nt][3] = fmaxf(acc[mt][nt][3] + bv1, 0.f);
        }
    }

    float*  proj = (float*)dyn;                 // [128][33] fp32
    __half* qvs  = (__half*)(dyn + 17408);      // [32 rows][264 halves]
    for (int i = tid; i < 128 * 33; i += 512) proj[i] = 0.f;
    for (int i = tid; i < 32 * 256; i += 512){
        int r = i >> 8, c = i & 255;
        qvs[r * 264 + c] = g_qvh[i];
    }
    __syncthreads();

    const uint32_t qbase = smem_u32(qvs);
    #pragma unroll
    for (int mt = 0; mt < 2; mt++){
        float cp[4][4];
        #pragma unroll
        for (int ht = 0; ht < 4; ht++)
            #pragma unroll
            for (int k = 0; k < 4; k++) cp[ht][k] = 0.f;
        #pragma unroll
        for (int j = 0; j < 4; j++){    // k16 chunks within this warp's 64 hid dims
            uint32_t bh[4][2];
            #pragma unroll
            for (int hg = 0; hg < 2; hg++){
                int hrow = hg * 16 + ((m_ >> 1) * 8) + r_;
                uint32_t addr = qbase + hrow * 528 + (nw * 64 + j * 16 + (m_ & 1) * 8) * 2;
                LDMX4(bh[hg*2][0], bh[hg*2][1], bh[hg*2+1][0], bh[hg*2+1][1], addr);
            }
            uint32_t ap[4] = {
                pack_h2(acc[mt][2*j  ][0], acc[mt][2*j  ][1]),
                pack_h2(acc[mt][2*j  ][2], acc[mt][2*j  ][3]),
                pack_h2(acc[mt][2*j+1][0], acc[mt][2*j+1][1]),
                pack_h2(acc[mt][2*j+1][2], acc[mt][2*j+1][3]) };
            #pragma unroll
            for (int ht = 0; ht < 4; ht++) mma16816(cp[ht], ap, bh[ht]);
        }
        int tok = mw * 32 + mt * 16 + rq;
        #pragma unroll
        for (int ht = 0; ht < 4; ht++){
            int hd = ht * 8 + cq;
            atomicAdd(&proj[tok * 33 + hd],           cp[ht][0]);
            atomicAdd(&proj[tok * 33 + hd + 1],       cp[ht][1]);
            atomicAdd(&proj[(tok + 8) * 33 + hd],     cp[ht][2]);
            atomicAdd(&proj[(tok + 8) * 33 + hd + 1], cp[ht][3]);
        }
    }
    __syncthreads();

    #pragma unroll
    for (int i = 0; i < 8; i++){
        int idx = tid + 512 * i;       // 0..4095
        int t = idx >> 5, hd = idx & 31;
        float s = proj[t * 33 + hd];
        size_t gt = m0 + t;
        if (hd < N_HEADS){
            g_L[gt * N_HEADS + hd] = s;
            atomicMax(&smax[hd], f2ord(s));
        } else {
            g_Vv[gt * N_HEADS + (hd - N_HEADS)] = s;
        }
    }
    __syncthreads();
    if (tid < N_HEADS) atomicMax(&g_logit_max[tid], smax[tid]);
}

// Sliding-window softmax-weighted mean, max over windows per head
__global__ __launch_bounds__(256)
void k_window(int n)
{
    __shared__ float    es [N_HEADS][328];
    __shared__ float    evs[N_HEADS][328];
    __shared__ float    mval[N_HEADS];
    __shared__ unsigned smax[N_HEADS];

    const int tid = threadIdx.x;
    const int w0  = blockIdx.x * 256;
    const int NW  = n - WINDOW + 1;

    if (tid < N_HEADS){
        mval[tid] = ord2f(g_logit_max[tid]);
        smax[tid] = f2ord(-INFINITY);
    }
    __syncthreads();

    int ntok = n - w0;
    if (ntok > 256 + WINDOW - 1) ntok = 256 + WINDOW - 1;
    for (int idx = tid; idx < ntok * N_HEADS; idx += 256){
        int h = idx & (N_HEADS - 1);
        int t = idx >> 4;
        size_t g = (size_t)(w0 + t) * N_HEADS + h;
        float e = expf(g_L[g] - mval[h]);
        es [h][t] = e;
        evs[h][t] = e * g_Vv[g];
    }
    __syncthreads();

    if (w0 + tid < NW){
        #pragma unroll 1
        for (int h = 0; h < N_HEADS; h++){
            float se = 0.f, sev = 0.f;
            #pragma unroll 16
            for (int j = 0; j < WINDOW; j++){
                se  += es [h][tid + j];
                sev += evs[h][tid + j];
            }
            atomicMax(&smax[h], f2ord(sev / se));
        }
    }
    __syncthreads();
    if (tid < N_HEADS) atomicMax(&g_score_max[tid], smax[tid]);
}

__global__ void k_final(float* out){
    int t = threadIdx.x;
    float s = (t < N_HEADS) ? ord2f(g_score_max[t]) : 0.f;
    #pragma unroll
    for (int off = 16; off; off >>= 1)
        s += __shfl_down_sync(0xffffffffu, s, off);
    if (t == 0) out[0] = s;
}

extern "C" void kernel_launch(void* const* d_in, const int* in_sizes, int n_in,
                              void* d_out, int out_size)
{
    const float* x  = (const float*)d_in[0];
    const float* w1 = (const float*)d_in[1];
    const float* b1 = (const float*)d_in[2];
    const float* qw = (const float*)d_in[3];
    const float* vw = (const float*)d_in[4];
    int n = in_sizes[0] / D_MODEL;

    cudaFuncSetAttribute(k_mlp, cudaFuncAttributeMaxDynamicSharedMemorySize, SMEM_DYN);

    k_init<<<1, 32>>>();
    k_prep_w<<<dim3(D_MODEL / 32, D_HID / 32), dim3(32, 8)>>>(w1);
    k_prep_qv<<<32, 256>>>(qw, vw);
    k_mlp<<<n / 128, 512, SMEM_DYN>>>(x, b1);
    int NW = n - WINDOW + 1;
    k_window<<<(NW + 255) / 256, 256>>>(n);
    k_final<<<1, 32>>>((float*)d_out);
}

// round 9
// speedup vs baseline: 1.3525x; 1.3525x over previous
#include <cuda_runtime.h>
#include <cuda_fp16.h>
#include <math.h>
#include <stdint.h>

#define D_MODEL 2048
#define D_HID   256
#define N_HEADS 16
#define WINDOW  64
#define MAX_TOK 131072

// ---------------- device scratch (no allocs allowed) ----------------
__device__ float    g_L [(size_t)MAX_TOK * N_HEADS];
__device__ float    g_Vv[(size_t)MAX_TOK * N_HEADS];
__device__ __half   g_w1h[(size_t)D_HID * D_MODEL];   // w1 transposed+fp16 [256][2048]
__device__ __half   g_qvh[32 * D_HID];                // [16 q | 16 v heads][256] fp16
__device__ unsigned g_logit_max[N_HEADS];
__device__ unsigned g_score_max[N_HEADS];

// ---------------- helpers ----------------
__device__ __forceinline__ unsigned f2ord(float f){
    unsigned u = __float_as_uint(f);
    return (u & 0x80000000u) ? ~u : (u | 0x80000000u);
}
__device__ __forceinline__ float ord2f(unsigned u){
    return (u & 0x80000000u) ? __uint_as_float(u & 0x7fffffffu) : __uint_as_float(~u);
}
__device__ __forceinline__ uint32_t smem_u32(const void* p){
    uint32_t a;
    asm("{ .reg .u64 t; cvta.to.shared.u64 t, %1; cvt.u32.u64 %0, t; }" : "=r"(a) : "l"(p));
    return a;
}
__device__ __forceinline__ uint32_t pack_h2(float lo, float hi){
    __half2 h = __floats2half2_rn(lo, hi);
    return *reinterpret_cast<uint32_t*>(&h);
}
__device__ __forceinline__ void mma16816(float* c, const uint32_t* a, const uint32_t* b){
    asm volatile(
        "mma.sync.aligned.m16n8k16.row.col.f32.f16.f16.f32 "
        "{%0,%1,%2,%3}, {%4,%5,%6,%7}, {%8,%9}, {%0,%1,%2,%3};"
        : "+f"(c[0]), "+f"(c[1]), "+f"(c[2]), "+f"(c[3])
        : "r"(a[0]), "r"(a[1]), "r"(a[2]), "r"(a[3]), "r"(b[0]), "r"(b[1]));
}
#define LDMX4(r0, r1, r2, r3, addr) \
    asm volatile("ldmatrix.sync.aligned.m8n8.x4.shared.b16 {%0,%1,%2,%3}, [%4];" \
                 : "=r"(r0), "=r"(r1), "=r"(r2), "=r"(r3) : "r"(addr))

// ---------------- kernels ----------------
__global__ void k_init(){
    int t = threadIdx.x;
    if (t < N_HEADS){
        unsigned ninf = ~0xFF800000u;  // f2ord(-inf)
        g_logit_max[t] = ninf;
        g_score_max[t] = ninf;
    }
}

// w1 [2048][256] fp32 -> g_w1h [256][2048] fp16
__global__ void k_prep_w(const float* __restrict__ w1){
    __shared__ float t[32][33];
    int k0 = blockIdx.x * 32, n0 = blockIdx.y * 32;
    int tx = threadIdx.x, ty = threadIdx.y;     // 32 x 8
    #pragma unroll
    for (int i = ty; i < 32; i += 8)
        t[i][tx] = w1[(size_t)(k0 + i) * D_HID + n0 + tx];
    __syncthreads();
    #pragma unroll
    for (int i = ty; i < 32; i += 8)
        g_w1h[(size_t)(n0 + i) * D_MODEL + k0 + tx] = __float2half_rn(t[tx][i]);
}

// qw,vw [16][256] fp32 -> g_qvh [32][256] fp16
__global__ void k_prep_qv(const float* __restrict__ qw, const float* __restrict__ vw){
    int i = blockIdx.x * 256 + threadIdx.x;
    if (i < 4096)      g_qvh[i] = __float2half_rn(qw[i]);
    else if (i < 8192) g_qvh[i] = __float2half_rn(vw[i - 4096]);
}

// ---------------- fused MLP + head projection (HMMA) ----------------
#define BK          32
#define KT_TILES    (D_MODEL / BK)      // 64
#define A32_PITCH   144
#define B_STRIDE    80
#define A16_PITCH   80
#define A32_BYTES   (128 * A32_PITCH)   // 18432
#define B_BYTES     (256 * B_STRIDE)    // 20480
#define STAGE_BYTES (A32_BYTES + B_BYTES)   // 38912
#define N_STAGES    4
#define A16_BYTES   (128 * A16_PITCH)   // 10240
#define A16_OFF     (N_STAGES * STAGE_BYTES)        // 155648
#define SMEM_DYN    (A16_OFF + 2 * A16_BYTES)       // 176128

__device__ __forceinline__ void load_stage(const float* __restrict__ x, size_t m0,
                                           int kt, uint32_t sA, uint32_t sB, int tid){
    #pragma unroll
    for (int i = 0; i < 2; i++){
        int ch  = tid + i * 512;            // 0..1023
        int row = ch >> 3, c = ch & 7;      // A: 128 rows x 8 chunks of 16B
        const float* src = x + (m0 + row) * D_MODEL + (size_t)kt * BK + c * 4;
        uint32_t dst = sA + row * A32_PITCH + c * 16;
        asm volatile("cp.async.cg.shared.global [%0], [%1], 16;" :: "r"(dst), "l"(src));
    }
    #pragma unroll
    for (int i = 0; i < 2; i++){
        int ch  = tid + i * 512;            // 0..1023
        // conflict-free STS phases: 8 distinct rows per phase (quads 5r mod 8 distinct);
        // per-warp global address set identical to naive mapping (coalescing unchanged)
        int row = ((ch >> 5) << 3) + (ch & 7);   // 0..255
        int cc  = (ch >> 3) & 3;                 // 0..3
        const char* src = (const char*)g_w1h + (size_t)row * (D_MODEL * 2) + kt * (BK * 2) + cc * 16;
        uint32_t dst = sB + row * B_STRIDE + cc * 16;
        asm volatile("cp.async.cg.shared.global [%0], [%1], 16;" :: "r"(dst), "l"(src));
    }
}

// CTA-cooperative fp32 -> fp16 conversion of one 128x32 A tile
__device__ __forceinline__ void convert_tile(const char* stage, char* a16, int tid){
    int row = tid & 127;
    int cg  = tid >> 7;                     // 0..3 (8-float group)
    const float4* p = (const float4*)(stage + row * A32_PITCH + cg * 32);
    float4 v0 = p[0], v1 = p[1];
    uint4 o;
    o.x = pack_h2(v0.x, v0.y); o.y = pack_h2(v0.z, v0.w);
    o.z = pack_h2(v1.x, v1.y); o.w = pack_h2(v1.z, v1.w);
    *(uint4*)(a16 + row * A16_PITCH + cg * 16) = o;
}

__global__ __launch_bounds__(512, 1)
void k_mlp(const float* __restrict__ x, const float* __restrict__ b1)
{
    extern __shared__ __align__(16) char dyn[];
    __shared__ unsigned smax[N_HEADS];

    const int tid  = threadIdx.x;
    const int wid  = tid >> 5;
    const int lane = tid & 31;
    const int mw   = wid >> 2;      // 0..3  M warp
    const int nw   = wid & 3;       // 0..3  N warp
    const int rq   = lane >> 2;     // 0..7
    const int cq   = (lane & 3) * 2;
    const int m_   = lane >> 3;     // ldmatrix matrix id
    const int r_   = lane & 7;      // ldmatrix row
    const size_t m0 = (size_t)blockIdx.x * 128;

    const uint32_t dbase = smem_u32(dyn);
    if (tid < N_HEADS) smax[tid] = ~0xFF800000u;

    float acc[2][8][4];
    #pragma unroll
    for (int mt = 0; mt < 2; mt++)
        #pragma unroll
        for (int nt = 0; nt < 8; nt++)
            #pragma unroll
            for (int k = 0; k < 4; k++) acc[mt][nt][k] = 0.f;

    // prologue: 3 stages in flight, convert tile 0
    #pragma unroll
    for (int p = 0; p < 3; p++){
        uint32_t st = dbase + p * STAGE_BYTES;
        load_stage(x, m0, p, st, st + A32_BYTES, tid);
        asm volatile("cp.async.commit_group;" ::: "memory");
    }
    asm volatile("cp.async.wait_group 2;" ::: "memory");
    __syncthreads();
    convert_tile(dyn, dyn + A16_OFF, tid);

    for (int kt = 0; kt < KT_TILES; kt++){
        asm volatile("cp.async.wait_group 1;" ::: "memory");
        __syncthreads();   // publishes: stage kt+1 data, A16[kt&1]; frees A16[(kt+1)&1]

        const uint32_t sB  = dbase + (kt % N_STAGES) * STAGE_BYTES + A32_BYTES;
        const uint32_t sAh = dbase + A16_OFF + (kt & 1) * A16_BYTES;

        uint32_t bf[8][2], af[2][4];

        // --- ks = 0: fragments first, fill gaps with convert ---
        #pragma unroll
        for (int ng = 0; ng < 4; ng++){
            int nrow = nw * 64 + ng * 16 + ((m_ >> 1) * 8) + r_;
            uint32_t addr = sB + nrow * B_STRIDE + ((m_ & 1) * 8) * 2;
            LDMX4(bf[ng*2][0], bf[ng*2][1], bf[ng*2+1][0], bf[ng*2+1][1], addr);
        }
        #pragma unroll
        for (int mt = 0; mt < 2; mt++){
            int arow = mw * 32 + mt * 16 + (m_ & 1) * 8 + r_;
            uint32_t aaddr = sAh + arow * A16_PITCH + ((m_ >> 1) * 8) * 2;
            LDMX4(af[mt][0], af[mt][1], af[mt][2], af[mt][3], aaddr);
        }

        if (kt + 1 < KT_TILES)
            convert_tile(dyn + ((kt + 1) % N_STAGES) * STAGE_BYTES,
                         dyn + A16_OFF + ((kt + 1) & 1) * A16_BYTES, tid);

        #pragma unroll
        for (int mt = 0; mt < 2; mt++)
            #pragma unroll
            for (int nt = 0; nt < 8; nt++)
                mma16816(acc[mt][nt], af[mt], bf[nt]);

        // --- refill pipeline under ks0's MMA shadow ---
        if (kt + 3 < KT_TILES){
            uint32_t ns = dbase + ((kt + 3) % N_STAGES) * STAGE_BYTES;
            load_stage(x, m0, kt + 3, ns, ns + A32_BYTES, tid);
        }
        asm volatile("cp.async.commit_group;" ::: "memory");

        // --- ks = 1: reuse same fragment registers ---
        #pragma unroll
        for (int ng = 0; ng < 4; ng++){
            int nrow = nw * 64 + ng * 16 + ((m_ >> 1) * 8) + r_;
            uint32_t addr = sB + nrow * B_STRIDE + (16 + (m_ & 1) * 8) * 2;
            LDMX4(bf[ng*2][0], bf[ng*2][1], bf[ng*2+1][0], bf[ng*2+1][1], addr);
        }
        #pragma unroll
        for (int mt = 0; mt < 2; mt++){
            int arow = mw * 32 + mt * 16 + (m_ & 1) * 8 + r_;
            uint32_t aaddr = sAh + arow * A16_PITCH + (16 + (m_ >> 1) * 8) * 2;
            LDMX4(af[mt][0], af[mt][1], af[mt][2], af[mt][3], aaddr);
        }
        #pragma unroll
        for (int mt = 0; mt < 2; mt++)
            #pragma unroll
            for (int nt = 0; nt < 8; nt++)
                mma16816(acc[mt][nt], af[mt], bf[nt]);
    }
    asm volatile("cp.async.wait_group 0;" ::: "memory");
    __syncthreads();   // mainloop smem reads done; reuse dyn below

    // ---------------- epilogue: bias + relu, then projection MMA ----------------
    #pragma unroll
    for (int nt = 0; nt < 8; nt++){
        int C = nw * 64 + nt * 8 + cq;
        float bv0 = __ldg(b1 + C), bv1 = __ldg(b1 + C + 1);
        #pragma unroll
        for (int mt = 0; mt < 2; mt++){
            acc[mt][nt][0] = fmaxf(acc[mt][nt][0] + bv0, 0.f);
            acc[mt][nt][1] = fmaxf(acc[mt][nt][1] + bv1, 0.f);
            acc[mt][nt][2] = fmaxf(acc[mt][nt][2] + bv0, 0.f);
            acc[mt][nt][3] = fmaxf(acc[mt][nt][3] + bv1, 0.f);
        }
    }

    float*  proj = (float*)dyn;                 // [128][33] fp32
    __half* qvs  = (__half*)(dyn + 17408);      // [32 rows][264 halves]
    for (int i = tid; i < 128 * 33; i += 512) proj[i] = 0.f;
    for (int i = tid; i < 32 * 256; i += 512){
        int r = i >> 8, c = i & 255;
        qvs[r * 264 + c] = g_qvh[i];
    }
    __syncthreads();

    const uint32_t qbase = smem_u32(qvs);
    #pragma unroll
    for (int mt = 0; mt < 2; mt++){
        float cp[4][4];
        #pragma unroll
        for (int ht = 0; ht < 4; ht++)
            #pragma unroll
            for (int k = 0; k < 4; k++) cp[ht][k] = 0.f;
        #pragma unroll
        for (int j = 0; j < 4; j++){    // k16 chunks within this warp's 64 hid dims
            uint32_t bh[4][2];
            #pragma unroll
            for (int hg = 0; hg < 2; hg++){
                int hrow = hg * 16 + ((m_ >> 1) * 8) + r_;
                uint32_t addr = qbase + hrow * 528 + (nw * 64 + j * 16 + (m_ & 1) * 8) * 2;
                LDMX4(bh[hg*2][0], bh[hg*2][1], bh[hg*2+1][0], bh[hg*2+1][1], addr);
            }
            uint32_t ap[4] = {
                pack_h2(acc[mt][2*j  ][0], acc[mt][2*j  ][1]),
                pack_h2(acc[mt][2*j  ][2], acc[mt][2*j  ][3]),
                pack_h2(acc[mt][2*j+1][0], acc[mt][2*j+1][1]),
                pack_h2(acc[mt][2*j+1][2], acc[mt][2*j+1][3]) };
            #pragma unroll
            for (int ht = 0; ht < 4; ht++) mma16816(cp[ht], ap, bh[ht]);
        }
        int tok = mw * 32 + mt * 16 + rq;
        #pragma unroll
        for (int ht = 0; ht < 4; ht++){
            int hd = ht * 8 + cq;
            atomicAdd(&proj[tok * 33 + hd],           cp[ht][0]);
            atomicAdd(&proj[tok * 33 + hd + 1],       cp[ht][1]);
            atomicAdd(&proj[(tok + 8) * 33 + hd],     cp[ht][2]);
            atomicAdd(&proj[(tok + 8) * 33 + hd + 1], cp[ht][3]);
        }
    }
    __syncthreads();

    #pragma unroll
    for (int i = 0; i < 8; i++){
        int idx = tid + 512 * i;       // 0..4095
        int t = idx >> 5, hd = idx & 31;
        float s = proj[t * 33 + hd];
        size_t gt = m0 + t;
        if (hd < N_HEADS){
            g_L[gt * N_HEADS + hd] = s;
            atomicMax(&smax[hd], f2ord(s));
        } else {
            g_Vv[gt * N_HEADS + (hd - N_HEADS)] = s;
        }
    }
    __syncthreads();
    if (tid < N_HEADS) atomicMax(&g_logit_max[tid], smax[tid]);
}

// Sliding-window softmax-weighted mean, max over windows per head
__global__ __launch_bounds__(256)
void k_window(int n)
{
    __shared__ float    es [N_HEADS][328];
    __shared__ float    evs[N_HEADS][328];
    __shared__ float    mval[N_HEADS];
    __shared__ unsigned smax[N_HEADS];

    const int tid = threadIdx.x;
    const int w0  = blockIdx.x * 256;
    const int NW  = n - WINDOW + 1;

    if (tid < N_HEADS){
        mval[tid] = ord2f(g_logit_max[tid]);
        smax[tid] = f2ord(-INFINITY);
    }
    __syncthreads();

    int ntok = n - w0;
    if (ntok > 256 + WINDOW - 1) ntok = 256 + WINDOW - 1;
    for (int idx = tid; idx < ntok * N_HEADS; idx += 256){
        int h = idx & (N_HEADS - 1);
        int t = idx >> 4;
        size_t g = (size_t)(w0 + t) * N_HEADS + h;
        float e = expf(g_L[g] - mval[h]);
        es [h][t] = e;
        evs[h][t] = e * g_Vv[g];
    }
    __syncthreads();

    if (w0 + tid < NW){
        #pragma unroll 1
        for (int h = 0; h < N_HEADS; h++){
            float se = 0.f, sev = 0.f;
            #pragma unroll 16
            for (int j = 0; j < WINDOW; j++){
                se  += es [h][tid + j];
                sev += evs[h][tid + j];
            }
            atomicMax(&smax[h], f2ord(sev / se));
        }
    }
    __syncthreads();
    if (tid < N_HEADS) atomicMax(&g_score_max[tid], smax[tid]);
}

__global__ void k_final(float* out){
    int t = threadIdx.x;
    float s = (t < N_HEADS) ? ord2f(g_score_max[t]) : 0.f;
    #pragma unroll
    for (int off = 16; off; off >>= 1)
        s += __shfl_down_sync(0xffffffffu, s, off);
    if (t == 0) out[0] = s;
}

extern "C" void kernel_launch(void* const* d_in, const int* in_sizes, int n_in,
                              void* d_out, int out_size)
{
    const float* x  = (const float*)d_in[0];
    const float* w1 = (const float*)d_in[1];
    const float* b1 = (const float*)d_in[2];
    const float* qw = (const float*)d_in[3];
    const float* vw = (const float*)d_in[4];
    int n = in_sizes[0] / D_MODEL;

    cudaFuncSetAttribute(k_mlp, cudaFuncAttributeMaxDynamicSharedMemorySize, SMEM_DYN);

    k_init<<<1, 32>>>();
    k_prep_w<<<dim3(D_MODEL / 32, D_HID / 32), dim3(32, 8)>>>(w1);
    k_prep_qv<<<32, 256>>>(qw, vw);
    k_mlp<<<n / 128, 512, SMEM_DYN>>>(x, b1);
    int NW = n - WINDOW + 1;
    k_window<<<(NW + 255) / 256, 256>>>(n);
    k_final<<<1, 32>>>((float*)d_out);
}